// round 12
// baseline (speedup 1.0000x reference)
#include <cuda_runtime.h>
#include <math.h>

#define RR   256
#define RH   129
#define ZP   130                 // padded zh stride (even -> float4-able)
#define NVOX 16777216            // 256^3
#define XS2  33280               // 256*ZP
#define CHS2 8519680             // 256*256*ZP
#define NBINS 32
#define MAXP  524288

// ---------------- scratch (device globals: allocation-free) ----------------
__device__ __align__(16) float2 g_gXY[NVOX];              // (Nx,Ny) interleaved [x][y][z]
__device__ __align__(16) float  g_gZ[NVOX];               // Nz [x][y][z]
__device__ __align__(16) float2 g_S[3u * CHS2 + 16];      // half-spectra [field][x][y][zh(pad)]
__device__ __align__(16) float2 g_P[CHS2 + 16];           // Phi spectrum [x][y][zh(pad)]
__device__ __align__(16) float4 g_pA[MAXP];               // sorted (px,py,pz,nx)
__device__ __align__(16) float2 g_pB[MAXP];               // sorted (ny,nz)
__device__ int    g_cnt[NBINS];                           // bin counters / cursors
__device__ float2 g_tw[256];                              // W256^m
__device__ double g_sum;
__device__ float  g_phi0;

// ---------------- complex helpers ----------------
__device__ __forceinline__ float2 cmul(float2 a, float2 b) {
    return make_float2(a.x * b.x - a.y * b.y, a.x * b.y + a.y * b.x);
}

template<int INV>
__device__ __forceinline__ void fft4(float2& a, float2& b, float2& c, float2& d) {
    float2 t0 = make_float2(a.x + c.x, a.y + c.y);
    float2 t1 = make_float2(a.x - c.x, a.y - c.y);
    float2 t2 = make_float2(b.x + d.x, b.y + d.y);
    float2 t3 = make_float2(b.x - d.x, b.y - d.y);
    float2 t3r = INV ? make_float2(-t3.y, t3.x) : make_float2(t3.y, -t3.x);
    a = make_float2(t0.x + t2.x, t0.y + t2.y);
    c = make_float2(t0.x - t2.x, t0.y - t2.y);
    b = make_float2(t1.x + t3r.x, t1.y + t3r.y);
    d = make_float2(t1.x - t3r.x, t1.y - t3r.y);
}

template<int INV>
__device__ __forceinline__ void fft16(float2 v[16]) {
    const float C1 = 0.9238795325112867f;
    const float S1 = 0.3826834323650898f;
    const float C2 = 0.7071067811865476f;
    const float sg = INV ? 1.f : -1.f;
    const float2 tw1 = make_float2( C1, sg * S1);
    const float2 tw2 = make_float2( C2, sg * C2);
    const float2 tw3 = make_float2( S1, sg * C1);
    const float2 tw4 = make_float2(0.f, sg * 1.f);
    const float2 tw6 = make_float2(-C2, sg * C2);
    const float2 tw9 = make_float2(-C1, -sg * S1);
#pragma unroll
    for (int n1 = 0; n1 < 4; n1++) fft4<INV>(v[n1], v[n1 + 4], v[n1 + 8], v[n1 + 12]);
    v[5]  = cmul(v[5],  tw1);  v[9]  = cmul(v[9],  tw2);  v[13] = cmul(v[13], tw3);
    v[6]  = cmul(v[6],  tw2);  v[10] = cmul(v[10], tw4);  v[14] = cmul(v[14], tw6);
    v[7]  = cmul(v[7],  tw3);  v[11] = cmul(v[11], tw6);  v[15] = cmul(v[15], tw9);
#pragma unroll
    for (int k2 = 0; k2 < 4; k2++) fft4<INV>(v[4 * k2], v[4 * k2 + 1], v[4 * k2 + 2], v[4 * k2 + 3]);
    float2 o[16];
#pragma unroll
    for (int k1 = 0; k1 < 4; k1++)
#pragma unroll
        for (int k2 = 0; k2 < 4; k2++) o[k2 + 4 * k1] = v[k1 + 4 * k2];
#pragma unroll
    for (int i = 0; i < 16; i++) v[i] = o[i];
}

// ---------------- kernels ----------------
__global__ void init_kernel() {
    int i = threadIdx.x;
    double a = -2.0 * 3.14159265358979323846 * (double)i / 256.0;
    double s, c;
    sincos(a, &s, &c);
    g_tw[i] = make_float2((float)c, (float)s);
    if (i < NBINS) g_cnt[i] = 0;
    if (i == 0) g_sum = 0.0;
}

// ---- counting sort by x-slab (bin = ix >> 3) ----
__global__ void count_kernel(const float* __restrict__ V, int P) {
    int p = blockIdx.x * blockDim.x + threadIdx.x;
    if (p >= P) return;
    int ix = (int)floorf(V[3 * p] * 256.f);
    atomicAdd(&g_cnt[ix >> 3], 1);
}

__global__ void scan_kernel() {
    int i = threadIdx.x;              // 32 threads
    int c = g_cnt[i];
    int s = c;
#pragma unroll
    for (int d = 1; d < 32; d <<= 1) {
        int t = __shfl_up_sync(0xffffffffu, s, d);
        if (i >= d) s += t;
    }
    g_cnt[i] = s - c;                 // exclusive prefix -> cursor
}

__global__ void reorder_kernel(const float* __restrict__ V, const float* __restrict__ N, int P) {
    int p = blockIdx.x * blockDim.x + threadIdx.x;
    if (p >= P) return;
    float px = V[3 * p + 0], py = V[3 * p + 1], pz = V[3 * p + 2];
    float nx = N[3 * p + 0], ny = N[3 * p + 1], nz = N[3 * p + 2];
    int ix = (int)floorf(px * 256.f);
    int pos = atomicAdd(&g_cnt[ix >> 3], 1);
    g_pA[pos] = make_float4(px, py, pz, nx);
    g_pB[pos] = make_float2(ny, nz);
}

// zero z-grid FIRST (evicted first), xy-grid SECOND (stays warm in L2 for scatter)
__global__ void zeroZ_kernel() {
    size_t i = (size_t)blockIdx.x * blockDim.x + threadIdx.x;
    ((float4*)g_gZ)[i] = make_float4(0.f, 0.f, 0.f, 0.f);
}
__global__ void zeroXY_kernel() {
    size_t i = (size_t)blockIdx.x * blockDim.x + threadIdx.x;
    ((float4*)g_gXY)[i] = make_float4(0.f, 0.f, 0.f, 0.f);
}

// scatter in slab-sorted order: concurrent CTAs touch only a few adjacent
// 6.3MB slab regions -> corner atomics are L2 hits.
__global__ void scatter_kernel(int P) {
    int p = blockIdx.x * blockDim.x + threadIdx.x;
    if (p >= P) return;
    float4 a = g_pA[p];
    float2 b = g_pB[p];
    float px = a.x * 256.f, py = a.y * 256.f, pz = a.z * 256.f;
    float nx = a.w, ny = b.x, nz = b.y;
    float flx = floorf(px), fly = floorf(py), flz = floorf(pz);
    int i0x = (int)flx, i0y = (int)fly, i0z = (int)flz;
    int i1x = ((int)ceilf(px)) & 255, i1y = ((int)ceilf(py)) & 255, i1z = ((int)ceilf(pz)) & 255;
    float f1x = px - flx, f1y = py - fly, f1z = pz - flz;
    float f0x = 1.f - f1x, f0y = 1.f - f1y, f0z = 1.f - f1z;
#pragma unroll
    for (int c = 0; c < 8; c++) {
        const int bx = (c >> 2) & 1, by = (c >> 1) & 1, bz = c & 1;
        float w = (bx ? f1x : f0x) * (by ? f1y : f0y) * (bz ? f1z : f0z);
        int ix = bx ? i1x : i0x, iy = by ? i1y : i0y, iz = bz ? i1z : i0z;
        int vox = ((ix << 8) + iy) * 256 + iz;
        atomicAdd(&g_gXY[vox].x, nx * w);
        atomicAdd(&g_gXY[vox].y, ny * w);
        atomicAdd(&g_gZ[vox], nz * w);
    }
}

// Forward z-FFT for channels x,y: the interleaved (Nx,Ny) line IS the complex
// signal Nx + i*Ny. One complex FFT + Hermitian unpack -> X_hat (g_S[0]),
// Y_hat (g_S[1]). 16 spatial lines per block.
__global__ void __launch_bounds__(256) zfwdXY_kernel() {
    __shared__ float2 tile[256][17];
    __shared__ float2 stw[256];
    stw[threadIdx.x] = g_tw[threadIdx.x];
    const size_t lineBase = (size_t)blockIdx.x * 16;
    for (int idx = threadIdx.x; idx < 16 * 128; idx += 256) {
        int q = idx & 127, l = idx >> 7;
        float4 d = *(const float4*)&g_gXY[(lineBase + l) * 256 + 2 * q];
        tile[2 * q + 0][l] = make_float2(d.x, d.y);
        tile[2 * q + 1][l] = make_float2(d.z, d.w);
    }
    __syncthreads();
    const int line = threadIdx.x & 15;
    const int w    = threadIdx.x >> 4;
    float2 v[16];
#pragma unroll
    for (int j = 0; j < 16; j++) v[j] = tile[w + 16 * j][line];
    fft16<0>(v);
#pragma unroll
    for (int k = 1; k < 16; k++) v[k] = cmul(v[k], stw[(w * k) & 255]);
#pragma unroll
    for (int k = 0; k < 16; k++) tile[w + 16 * k][line] = v[k];
    __syncthreads();
#pragma unroll
    for (int j = 0; j < 16; j++) v[j] = tile[j + 16 * w][line];
    fft16<0>(v);
    __syncthreads();
#pragma unroll
    for (int j = 0; j < 16; j++) tile[w + 16 * j][line] = v[j];   // Z[e=w+16j]
    __syncthreads();
    // X_hat[k]=(Z[k]+conj(Z[m]))/2, Y_hat[k]=(Z[k]-conj(Z[m]))/2i, m=(256-k)&255
    for (int idx = threadIdx.x; idx < 16 * 64; idx += 256) {
        int q = idx & 63, l = idx >> 6;
        int k0 = 2 * q;
        float2 z0 = tile[k0][l],               z1 = tile[k0 + 1][l];
        float2 m0 = tile[(256 - k0) & 255][l], m1 = tile[255 - k0][l];
        float4 A = make_float4(0.5f * (z0.x + m0.x), 0.5f * (z0.y - m0.y),
                               0.5f * (z1.x + m1.x), 0.5f * (z1.y - m1.y));
        float4 B = make_float4(0.5f * (z0.y + m0.y), 0.5f * (m0.x - z0.x),
                               0.5f * (z1.y + m1.y), 0.5f * (m1.x - z1.x));
        *(float4*)&g_S[(lineBase + l) * ZP + k0]        = A;
        *(float4*)&g_S[CHS2 + (lineBase + l) * ZP + k0] = B;
    }
    if (threadIdx.x < 16) {
        int l = threadIdx.x;
        float2 z = tile[128][l];
        g_S[(lineBase + l) * ZP + 128]        = make_float2(z.x, 0.f);
        g_S[CHS2 + (lineBase + l) * ZP + 128] = make_float2(z.y, 0.f);
    }
}

// Pack-2 real forward z-FFT for channel z (fz folded) -> g_S[2].
__global__ void __launch_bounds__(256) zfwdZ_kernel() {
    __shared__ float2 tile[256][17];
    __shared__ float2 stw[256];
    stw[threadIdx.x] = g_tw[threadIdx.x];
    const size_t lineBase = (size_t)blockIdx.x * 32;
    for (int idx = threadIdx.x; idx < 16 * 64; idx += 256) {
        int q = idx & 63, l = idx >> 6;
        float4 a = *(const float4*)&g_gZ[(lineBase + 2 * l) * 256 + 4 * q];
        float4 b = *(const float4*)&g_gZ[(lineBase + 2 * l + 1) * 256 + 4 * q];
        tile[4 * q + 0][l] = make_float2(a.x, b.x);
        tile[4 * q + 1][l] = make_float2(a.y, b.y);
        tile[4 * q + 2][l] = make_float2(a.z, b.z);
        tile[4 * q + 3][l] = make_float2(a.w, b.w);
    }
    __syncthreads();
    const int line = threadIdx.x & 15;
    const int w    = threadIdx.x >> 4;
    float2 v[16];
#pragma unroll
    for (int j = 0; j < 16; j++) v[j] = tile[w + 16 * j][line];
    fft16<0>(v);
#pragma unroll
    for (int k = 1; k < 16; k++) v[k] = cmul(v[k], stw[(w * k) & 255]);
#pragma unroll
    for (int k = 0; k < 16; k++) tile[w + 16 * k][line] = v[k];
    __syncthreads();
#pragma unroll
    for (int j = 0; j < 16; j++) v[j] = tile[j + 16 * w][line];
    fft16<0>(v);
    __syncthreads();
#pragma unroll
    for (int j = 0; j < 16; j++) tile[w + 16 * j][line] = v[j];
    __syncthreads();
    for (int idx = threadIdx.x; idx < 16 * 64; idx += 256) {
        int q = idx & 63, l = idx >> 6;
        int k0 = 2 * q;
        float2 z0 = tile[k0][l],               z1 = tile[k0 + 1][l];
        float2 m0 = tile[(256 - k0) & 255][l], m1 = tile[255 - k0][l];
        float f0 = (float)k0, f1 = (float)(k0 + 1);
        float4 A = make_float4(0.5f * f0 * (z0.x + m0.x), 0.5f * f0 * (z0.y - m0.y),
                               0.5f * f1 * (z1.x + m1.x), 0.5f * f1 * (z1.y - m1.y));
        float4 B = make_float4(0.5f * f0 * (z0.y + m0.y), 0.5f * f0 * (m0.x - z0.x),
                               0.5f * f1 * (z1.y + m1.y), 0.5f * f1 * (m1.x - z1.x));
        *(float4*)&g_S[2 * (size_t)CHS2 + (lineBase + 2 * l) * ZP + k0]     = A;
        *(float4*)&g_S[2 * (size_t)CHS2 + (lineBase + 2 * l + 1) * ZP + k0] = B;
    }
    if (threadIdx.x < 16) {
        int l = threadIdx.x;
        float2 z = tile[128][l];
        g_S[2 * (size_t)CHS2 + (lineBase + 2 * l) * ZP + 128]     = make_float2(z.x * 128.f, 0.f);
        g_S[2 * (size_t)CHS2 + (lineBase + 2 * l + 1) * ZP + 128] = make_float2(z.y * 128.f, 0.f);
    }
}

// Unified forward y-pass:
//   blockIdx.z == 0 : field 0 (X_hat), plain y-FFT in place.
//   blockIdx.z == 1 : fields 1,2 -> fy*FFTy(Y_hat) + FFTy(fz*Z_hat) into g_S[1].
__global__ void __launch_bounds__(256) yfwd_kernel() {
    __shared__ float2 tile[256][17];
    __shared__ float2 stw[256];
    stw[threadIdx.x] = g_tw[threadIdx.x];
    const int line = threadIdx.x & 15;
    const int w    = threadIdx.x >> 4;
    const int zl   = blockIdx.x * 16 + line;
    const bool ok  = zl < RH;
    const size_t rowoff = (size_t)blockIdx.y * XS2 + (size_t)zl;
    const bool merged = blockIdx.z == 1;

    float2 acc[16];
    float2 v[16];
    {
        const float2* row = g_S + (merged ? (size_t)CHS2 : 0) + rowoff;
#pragma unroll
        for (int j = 0; j < 16; j++) v[j] = row[(size_t)(w + 16 * j) * ZP];
    }
    __syncthreads();   // stw ready
    fft16<0>(v);
#pragma unroll
    for (int k = 1; k < 16; k++) v[k] = cmul(v[k], stw[(w * k) & 255]);
#pragma unroll
    for (int k = 0; k < 16; k++) tile[w + 16 * k][line] = v[k];
    __syncthreads();
#pragma unroll
    for (int j = 0; j < 16; j++) v[j] = tile[j + 16 * w][line];
    fft16<0>(v);
    if (!merged) {
        if (ok) {
            float2* dst = g_S + rowoff;
#pragma unroll
            for (int j = 0; j < 16; j++) dst[(size_t)(w + 16 * j) * ZP] = v[j];
        }
        return;
    }
#pragma unroll
    for (int j = 0; j < 16; j++) {
        int e = w + 16 * j;
        float fy = (float)e - (e >= 128 ? 256.f : 0.f);
        acc[j] = make_float2(v[j].x * fy, v[j].y * fy);
    }
    {
        const float2* row = g_S + 2 * (size_t)CHS2 + rowoff;
#pragma unroll
        for (int j = 0; j < 16; j++) v[j] = row[(size_t)(w + 16 * j) * ZP];
    }
    __syncthreads();   // phase-1 tile reads done
    fft16<0>(v);
#pragma unroll
    for (int k = 1; k < 16; k++) v[k] = cmul(v[k], stw[(w * k) & 255]);
#pragma unroll
    for (int k = 0; k < 16; k++) tile[w + 16 * k][line] = v[k];
    __syncthreads();
#pragma unroll
    for (int j = 0; j < 16; j++) v[j] = tile[j + 16 * w][line];
    fft16<0>(v);
    if (ok) {
        float2* dst = g_S + CHS2 + rowoff;
#pragma unroll
        for (int j = 0; j < 16; j++)
            dst[(size_t)(w + 16 * j) * ZP] = make_float2(acc[j].x + v[j].x, acc[j].y + v[j].y);
    }
}

// Inverse y-pass on g_P.
__global__ void __launch_bounds__(256) yinv_kernel() {
    __shared__ float2 tile[256][17];
    __shared__ float2 stw[256];
    stw[threadIdx.x] = g_tw[threadIdx.x];
    const int line = threadIdx.x & 15;
    const int w    = threadIdx.x >> 4;
    const int zl   = blockIdx.x * 16 + line;
    const bool ok  = zl < RH;
    float2* row = g_P + (size_t)blockIdx.y * XS2 + (size_t)zl;
    float2 v[16];
#pragma unroll
    for (int j = 0; j < 16; j++) v[j] = row[(size_t)(w + 16 * j) * ZP];
    __syncthreads();   // stw ready
    fft16<1>(v);
#pragma unroll
    for (int k = 1; k < 16; k++) {
        float2 t = stw[(w * k) & 255];
        t.y = -t.y;
        v[k] = cmul(v[k], t);
    }
#pragma unroll
    for (int k = 0; k < 16; k++) tile[w + 16 * k][line] = v[k];
    __syncthreads();
#pragma unroll
    for (int j = 0; j < 16; j++) v[j] = tile[j + 16 * w][line];
    fft16<1>(v);
    if (ok) {
#pragma unroll
        for (int j = 0; j < 16; j++) row[(size_t)(w + 16 * j) * ZP] = v[j];
    }
}

// Fused forward-x FFT (2 fields) + spectral combine + inverse-x FFT.
__global__ void __launch_bounds__(256, 2) xfuse_kernel() {
    __shared__ float2 tile[256][17];
    __shared__ float2 stw[256];
    stw[threadIdx.x] = g_tw[threadIdx.x];
    const int line = threadIdx.x & 15;
    const int w    = threadIdx.x >> 4;
    const int y    = blockIdx.y;
    const int zl   = blockIdx.x * 16 + line;
    const bool ok  = zl < RH;
    const size_t rowbase = (size_t)y * ZP + (size_t)zl;

    const float fy = (float)(y < 128 ? y : y - 256);
    const float fz = (float)zl;
    const float sigf = 20.f / 256.f;
    const float twopi = 6.283185307179586f;
    float aG[16];
#pragma unroll
    for (int j = 0; j < 16; j++) {
        int e = w + 16 * j;
        float fx = (float)e - (e >= 128 ? 256.f : 0.f);
        float d2 = fx * fx + fy * fy + fz * fz;
        aG[j] = twopi * __expf(-0.5f * sigf * sigf * d2);
    }
    float2 acc[16];
#pragma unroll
    for (int j = 0; j < 16; j++) acc[j] = make_float2(0.f, 0.f);

#pragma unroll
    for (int c = 0; c < 2; c++) {
        const float2* src = g_S + (size_t)c * CHS2 + rowbase;
        float2 v[16];
#pragma unroll
        for (int j = 0; j < 16; j++) v[j] = src[(size_t)(w + 16 * j) * XS2];
        __syncthreads();   // prev-iter tile reads done (and stw on iter 0)
        fft16<0>(v);
#pragma unroll
        for (int k = 1; k < 16; k++) v[k] = cmul(v[k], stw[(w * k) & 255]);
#pragma unroll
        for (int k = 0; k < 16; k++) tile[w + 16 * k][line] = v[k];
        __syncthreads();
#pragma unroll
        for (int j = 0; j < 16; j++) v[j] = tile[j + 16 * w][line];
        fft16<0>(v);
#pragma unroll
        for (int j = 0; j < 16; j++) {
            float fc = 1.f;
            if (c == 0) {
                int e = w + 16 * j;
                fc = (float)e - (e >= 128 ? 256.f : 0.f);
            }
            float coef = aG[j] * fc;
            acc[j].x += coef * v[j].y;
            acc[j].y -= coef * v[j].x;
        }
    }
#pragma unroll
    for (int j = 0; j < 16; j++) {
        int e = w + 16 * j;
        float fx = (float)e - (e >= 128 ? 256.f : 0.f);
        float d2 = fx * fx + fy * fy + fz * fz;
        float invL = 1.f / (-(twopi * twopi) * d2 + 1e-6f);
        acc[j].x *= invL;
        acc[j].y *= invL;
    }
    fft16<1>(acc);
#pragma unroll
    for (int k = 1; k < 16; k++) {
        float2 t = stw[(w * k) & 255];
        t.y = -t.y;
        acc[k] = cmul(acc[k], t);
    }
    __syncthreads();   // last fwd-stage tile reads done
#pragma unroll
    for (int k = 0; k < 16; k++) tile[w + 16 * k][line] = acc[k];
    __syncthreads();
#pragma unroll
    for (int j = 0; j < 16; j++) acc[j] = tile[j + 16 * w][line];
    fft16<1>(acc);
    if (ok) {
        float2* dst = g_P + rowbase;
#pragma unroll
        for (int j = 0; j < 16; j++) dst[(size_t)(w + 16 * j) * XS2] = acc[j];
    }
}

// Pack-2 inverse real FFT along z: 32 real output lines/block as 16 complex.
__global__ void __launch_bounds__(256) zinv_kernel(float* __restrict__ out) {
    __shared__ float2 tile[256][17];
    __shared__ float2 stw[256];
    stw[threadIdx.x] = g_tw[threadIdx.x];
    const size_t lineBase = (size_t)blockIdx.x * 32;
    for (int idx = threadIdx.x; idx < 16 * 64; idx += 256) {
        int q = idx & 63, l = idx >> 6;
        int k0 = 2 * q;
        float4 a4 = *(const float4*)&g_P[(lineBase + 2 * l) * ZP + k0];
        float4 b4 = *(const float4*)&g_P[(lineBase + 2 * l + 1) * ZP + k0];
        tile[k0][l]     = make_float2(a4.x - b4.y, a4.y + b4.x);
        tile[k0 + 1][l] = make_float2(a4.z - b4.w, a4.w + b4.z);
        if (k0 > 0) tile[256 - k0][l] = make_float2(a4.x + b4.y, b4.x - a4.y);
        tile[255 - k0][l] = make_float2(a4.z + b4.w, b4.z - a4.w);
    }
    if (threadIdx.x < 16) {
        int l = threadIdx.x;
        float2 A = g_P[(lineBase + 2 * l) * ZP + 128];
        float2 B = g_P[(lineBase + 2 * l + 1) * ZP + 128];
        tile[128][l] = make_float2(A.x - B.y, A.y + B.x);
    }
    __syncthreads();
    const int line = threadIdx.x & 15;
    const int w    = threadIdx.x >> 4;
    float2 v[16];
#pragma unroll
    for (int j = 0; j < 16; j++) v[j] = tile[w + 16 * j][line];
    fft16<1>(v);
#pragma unroll
    for (int k = 1; k < 16; k++) {
        float2 t = stw[(w * k) & 255];
        t.y = -t.y;
        v[k] = cmul(v[k], t);
    }
#pragma unroll
    for (int k = 0; k < 16; k++) tile[w + 16 * k][line] = v[k];
    __syncthreads();
#pragma unroll
    for (int j = 0; j < 16; j++) v[j] = tile[j + 16 * w][line];
    fft16<1>(v);
    __syncthreads();
#pragma unroll
    for (int j = 0; j < 16; j++) tile[w + 16 * j][line] = v[j];
    __syncthreads();
    const float sc = 1.f / 16777216.f;
    for (int idx = threadIdx.x; idx < 16 * 64; idx += 256) {
        int q = idx & 63, l = idx >> 6;
        float2 z0 = tile[4 * q + 0][l], z1 = tile[4 * q + 1][l];
        float2 z2 = tile[4 * q + 2][l], z3 = tile[4 * q + 3][l];
        *(float4*)&out[(lineBase + 2 * l) * 256 + 4 * q] =
            make_float4(z0.x * sc, z1.x * sc, z2.x * sc, z3.x * sc);
        *(float4*)&out[(lineBase + 2 * l + 1) * 256 + 4 * q] =
            make_float4(z0.y * sc, z1.y * sc, z2.y * sc, z3.y * sc);
    }
}

__global__ void interp_kernel(const float* __restrict__ V, const float* __restrict__ phi, int P) {
    int p = blockIdx.x * 256 + threadIdx.x;
    float val = 0.f;
    if (p < P) {
        float px = V[3 * p + 0] * 256.f, py = V[3 * p + 1] * 256.f, pz = V[3 * p + 2] * 256.f;
        float flx = floorf(px), fly = floorf(py), flz = floorf(pz);
        int i0x = (int)flx, i0y = (int)fly, i0z = (int)flz;
        int i1x = ((int)ceilf(px)) & 255, i1y = ((int)ceilf(py)) & 255, i1z = ((int)ceilf(pz)) & 255;
        float f1x = px - flx, f1y = py - fly, f1z = pz - flz;
        float f0x = 1.f - f1x, f0y = 1.f - f1y, f0z = 1.f - f1z;
#pragma unroll
        for (int c = 0; c < 8; c++) {
            const int bx = (c >> 2) & 1, by = (c >> 1) & 1, bz = c & 1;
            float w = (bx ? f1x : f0x) * (by ? f1y : f0y) * (bz ? f1z : f0z);
            int ix = bx ? i1x : i0x, iy = by ? i1y : i0y, iz = bz ? i1z : i0z;
            val += w * phi[((ix << 8) + iy) * 256 + iz];
        }
    }
    __shared__ float red[256];
    red[threadIdx.x] = val;
    __syncthreads();
    for (int s = 128; s > 0; s >>= 1) {
        if (threadIdx.x < s) red[threadIdx.x] += red[threadIdx.x + s];
        __syncthreads();
    }
    if (threadIdx.x == 0) atomicAdd(&g_sum, (double)red[0]);
    if (p == 0) g_phi0 = phi[0];
}

__global__ void finalize_kernel(float* __restrict__ out, int P) {
    float m = (float)(g_sum / (double)P);
    float scale = -0.5f / fabsf(g_phi0 - m);
    size_t i = (size_t)blockIdx.x * 256 + threadIdx.x;
    float4 v = ((float4*)out)[i];
    v.x = (v.x - m) * scale;
    v.y = (v.y - m) * scale;
    v.z = (v.z - m) * scale;
    v.w = (v.w - m) * scale;
    ((float4*)out)[i] = v;
}

// ---------------- launch ----------------
extern "C" void kernel_launch(void* const* d_in, const int* in_sizes, int n_in,
                              void* d_out, int out_size) {
    const float* V = (const float*)d_in[0];
    const float* N = (const float*)d_in[1];
    float* out = (float*)d_out;
    int P = in_sizes[0] / 3;

    init_kernel<<<1, 256>>>();
    // counting sort by x-slab (before zeroing so L2 warmth survives)
    count_kernel<<<(P + 255) / 256, 256>>>(V, P);
    scan_kernel<<<1, 32>>>();
    reorder_kernel<<<(P + 255) / 256, 256>>>(V, N, P);

    zeroZ_kernel<<<(NVOX / 4) / 256, 256>>>();         // evicted first
    zeroXY_kernel<<<(2 * NVOX / 4) / 256, 256>>>();    // warm in L2 for scatter
    scatter_kernel<<<(P + 127) / 128, 128>>>(P);

    // forward z: xy channels via cross-channel complex packing; z via pack-2 (+fz)
    zfwdXY_kernel<<<65536 / 16, 256>>>();
    zfwdZ_kernel<<<65536 / 32, 256>>>();
    // unified forward y (z=0: field 0; z=1: merged fields 1+2)
    yfwd_kernel<<<dim3(9, 256, 2), 256>>>();
    // fused forward x (2 fields) + spectral combine + inverse x -> g_P
    xfuse_kernel<<<dim3(9, 256), 256>>>();
    // inverse y on g_P
    yinv_kernel<<<dim3(9, 256), 256>>>();
    // inverse z (pack-2) -> raw phi in out
    zinv_kernel<<<65536 / 32, 256>>>(out);

    interp_kernel<<<(P + 255) / 256, 256>>>(V, out, P);
    finalize_kernel<<<NVOX / 4 / 256, 256>>>(out, P);
}

// round 15
// speedup vs baseline: 1.4118x; 1.4118x over previous
#include <cuda_runtime.h>
#include <math.h>

#define RR   256
#define RH   129
#define ZP   130                 // padded zh stride (even -> float4-able)
#define NVOX 16777216            // 256^3
#define XS2  33280               // 256*ZP
#define CHS2 8519680             // 256*256*ZP

// ---------------- scratch (device globals: allocation-free) ----------------
__device__ __align__(16) float2 g_gXY[NVOX];              // (Nx,Ny) interleaved [x][y][z]
__device__ __align__(16) float  g_gZ[NVOX];               // Nz [x][y][z]
__device__ __align__(16) float2 g_S[3u * CHS2 + 16];      // half-spectra [field][x][y][zh(pad)]
__device__ __align__(16) float2 g_P[CHS2 + 16];           // Phi spectrum [x][y][zh(pad)]
__device__ float2 g_tw[256];                              // W256^m
__device__ double g_sum;
__device__ float  g_phi0;

// ---------------- helpers ----------------
__device__ __forceinline__ float2 cmul(float2 a, float2 b) {
    return make_float2(a.x * b.x - a.y * b.y, a.x * b.y + a.y * b.x);
}

// native 64-bit vector reduction (sm_90+): one LSU op for the (x,y) pair
__device__ __forceinline__ void red_v2(float2* p, float a, float b) {
    asm volatile("red.global.add.v2.f32 [%0], {%1, %2};" :: "l"(p), "f"(a), "f"(b) : "memory");
}

template<int INV>
__device__ __forceinline__ void fft4(float2& a, float2& b, float2& c, float2& d) {
    float2 t0 = make_float2(a.x + c.x, a.y + c.y);
    float2 t1 = make_float2(a.x - c.x, a.y - c.y);
    float2 t2 = make_float2(b.x + d.x, b.y + d.y);
    float2 t3 = make_float2(b.x - d.x, b.y - d.y);
    float2 t3r = INV ? make_float2(-t3.y, t3.x) : make_float2(t3.y, -t3.x);
    a = make_float2(t0.x + t2.x, t0.y + t2.y);
    c = make_float2(t0.x - t2.x, t0.y - t2.y);
    b = make_float2(t1.x + t3r.x, t1.y + t3r.y);
    d = make_float2(t1.x - t3r.x, t1.y - t3r.y);
}

template<int INV>
__device__ __forceinline__ void fft16(float2 v[16]) {
    const float C1 = 0.9238795325112867f;
    const float S1 = 0.3826834323650898f;
    const float C2 = 0.7071067811865476f;
    const float sg = INV ? 1.f : -1.f;
    const float2 tw1 = make_float2( C1, sg * S1);
    const float2 tw2 = make_float2( C2, sg * C2);
    const float2 tw3 = make_float2( S1, sg * C1);
    const float2 tw4 = make_float2(0.f, sg * 1.f);
    const float2 tw6 = make_float2(-C2, sg * C2);
    const float2 tw9 = make_float2(-C1, -sg * S1);
#pragma unroll
    for (int n1 = 0; n1 < 4; n1++) fft4<INV>(v[n1], v[n1 + 4], v[n1 + 8], v[n1 + 12]);
    v[5]  = cmul(v[5],  tw1);  v[9]  = cmul(v[9],  tw2);  v[13] = cmul(v[13], tw3);
    v[6]  = cmul(v[6],  tw2);  v[10] = cmul(v[10], tw4);  v[14] = cmul(v[14], tw6);
    v[7]  = cmul(v[7],  tw3);  v[11] = cmul(v[11], tw6);  v[15] = cmul(v[15], tw9);
#pragma unroll
    for (int k2 = 0; k2 < 4; k2++) fft4<INV>(v[4 * k2], v[4 * k2 + 1], v[4 * k2 + 2], v[4 * k2 + 3]);
    float2 o[16];
#pragma unroll
    for (int k1 = 0; k1 < 4; k1++)
#pragma unroll
        for (int k2 = 0; k2 < 4; k2++) o[k2 + 4 * k1] = v[k1 + 4 * k2];
#pragma unroll
    for (int i = 0; i < 16; i++) v[i] = o[i];
}

// ---------------- kernels ----------------
__global__ void init_kernel() {
    int i = threadIdx.x;
    double a = -2.0 * 3.14159265358979323846 * (double)i / 256.0;
    double s, c;
    sincos(a, &s, &c);
    g_tw[i] = make_float2((float)c, (float)s);
    if (i == 0) g_sum = 0.0;
}

// one launch: blocks [0, 16384) zero g_gZ (evicted first), the rest zero g_gXY
// (zeroed last -> warm in L2 when scatter runs).
__global__ void zero_kernel() {
    size_t b = blockIdx.x;
    const float4 z4 = make_float4(0.f, 0.f, 0.f, 0.f);
    if (b < 16384) {
        ((float4*)g_gZ)[b * 256 + threadIdx.x] = z4;
    } else {
        ((float4*)g_gXY)[(b - 16384) * 256 + threadIdx.x] = z4;
    }
}

__global__ void scatter_kernel(const float* __restrict__ V, const float* __restrict__ N, int P) {
    int p = blockIdx.x * blockDim.x + threadIdx.x;
    if (p >= P) return;
    float px = V[3 * p + 0] * 256.f, py = V[3 * p + 1] * 256.f, pz = V[3 * p + 2] * 256.f;
    float nx = N[3 * p + 0], ny = N[3 * p + 1], nz = N[3 * p + 2];
    float flx = floorf(px), fly = floorf(py), flz = floorf(pz);
    int i0x = (int)flx, i0y = (int)fly, i0z = (int)flz;
    int i1x = ((int)ceilf(px)) & 255, i1y = ((int)ceilf(py)) & 255, i1z = ((int)ceilf(pz)) & 255;
    float f1x = px - flx, f1y = py - fly, f1z = pz - flz;
    float f0x = 1.f - f1x, f0y = 1.f - f1y, f0z = 1.f - f1z;
#pragma unroll
    for (int c = 0; c < 8; c++) {
        const int bx = (c >> 2) & 1, by = (c >> 1) & 1, bz = c & 1;
        float w = (bx ? f1x : f0x) * (by ? f1y : f0y) * (bz ? f1z : f0z);
        int ix = bx ? i1x : i0x, iy = by ? i1y : i0y, iz = bz ? i1z : i0z;
        int vox = ((ix << 8) + iy) * 256 + iz;
        red_v2(&g_gXY[vox], nx * w, ny * w);   // single RED.64
        atomicAdd(&g_gZ[vox], nz * w);
    }
}

// Unified forward z-FFT:
//   blocks [0, 4096): channels x,y via cross-channel complex packing
//     ((Nx,Ny) line IS Nx + i*Ny; one FFT + Hermitian unpack -> g_S[0], g_S[1]),
//     16 spatial lines per block.
//   blocks [4096, 6144): channel z via pack-2 real FFT (fz folded) -> g_S[2],
//     32 spatial lines per block.
__global__ void __launch_bounds__(256) zfwd_kernel() {
    __shared__ float2 tile[256][17];
    __shared__ float2 stw[256];
    stw[threadIdx.x] = g_tw[threadIdx.x];
    const int line = threadIdx.x & 15;
    const int w    = threadIdx.x >> 4;
    float2 v[16];

    if (blockIdx.x < 4096) {
        const size_t lineBase = (size_t)blockIdx.x * 16;
        for (int idx = threadIdx.x; idx < 16 * 128; idx += 256) {
            int q = idx & 127, l = idx >> 7;
            float4 d = *(const float4*)&g_gXY[(lineBase + l) * 256 + 2 * q];
            tile[2 * q + 0][l] = make_float2(d.x, d.y);
            tile[2 * q + 1][l] = make_float2(d.z, d.w);
        }
        __syncthreads();
#pragma unroll
        for (int j = 0; j < 16; j++) v[j] = tile[w + 16 * j][line];
        fft16<0>(v);
#pragma unroll
        for (int k = 1; k < 16; k++) v[k] = cmul(v[k], stw[(w * k) & 255]);
#pragma unroll
        for (int k = 0; k < 16; k++) tile[w + 16 * k][line] = v[k];
        __syncthreads();
#pragma unroll
        for (int j = 0; j < 16; j++) v[j] = tile[j + 16 * w][line];
        fft16<0>(v);
        __syncthreads();
#pragma unroll
        for (int j = 0; j < 16; j++) tile[w + 16 * j][line] = v[j];   // Z[e=w+16j]
        __syncthreads();
        // X_hat[k]=(Z[k]+conj(Z[m]))/2, Y_hat[k]=(Z[k]-conj(Z[m]))/2i, m=(256-k)&255
        for (int idx = threadIdx.x; idx < 16 * 64; idx += 256) {
            int q = idx & 63, l = idx >> 6;
            int k0 = 2 * q;
            float2 z0 = tile[k0][l],               z1 = tile[k0 + 1][l];
            float2 m0 = tile[(256 - k0) & 255][l], m1 = tile[255 - k0][l];
            float4 A = make_float4(0.5f * (z0.x + m0.x), 0.5f * (z0.y - m0.y),
                                   0.5f * (z1.x + m1.x), 0.5f * (z1.y - m1.y));
            float4 B = make_float4(0.5f * (z0.y + m0.y), 0.5f * (m0.x - z0.x),
                                   0.5f * (z1.y + m1.y), 0.5f * (m1.x - z1.x));
            *(float4*)&g_S[(lineBase + l) * ZP + k0]        = A;
            *(float4*)&g_S[CHS2 + (lineBase + l) * ZP + k0] = B;
        }
        if (threadIdx.x < 16) {
            int l = threadIdx.x;
            float2 z = tile[128][l];
            g_S[(lineBase + l) * ZP + 128]        = make_float2(z.x, 0.f);
            g_S[CHS2 + (lineBase + l) * ZP + 128] = make_float2(z.y, 0.f);
        }
    } else {
        const size_t lineBase = (size_t)(blockIdx.x - 4096) * 32;
        for (int idx = threadIdx.x; idx < 16 * 64; idx += 256) {
            int q = idx & 63, l = idx >> 6;
            float4 a = *(const float4*)&g_gZ[(lineBase + 2 * l) * 256 + 4 * q];
            float4 b = *(const float4*)&g_gZ[(lineBase + 2 * l + 1) * 256 + 4 * q];
            tile[4 * q + 0][l] = make_float2(a.x, b.x);
            tile[4 * q + 1][l] = make_float2(a.y, b.y);
            tile[4 * q + 2][l] = make_float2(a.z, b.z);
            tile[4 * q + 3][l] = make_float2(a.w, b.w);
        }
        __syncthreads();
#pragma unroll
        for (int j = 0; j < 16; j++) v[j] = tile[w + 16 * j][line];
        fft16<0>(v);
#pragma unroll
        for (int k = 1; k < 16; k++) v[k] = cmul(v[k], stw[(w * k) & 255]);
#pragma unroll
        for (int k = 0; k < 16; k++) tile[w + 16 * k][line] = v[k];
        __syncthreads();
#pragma unroll
        for (int j = 0; j < 16; j++) v[j] = tile[j + 16 * w][line];
        fft16<0>(v);
        __syncthreads();
#pragma unroll
        for (int j = 0; j < 16; j++) tile[w + 16 * j][line] = v[j];
        __syncthreads();
        for (int idx = threadIdx.x; idx < 16 * 64; idx += 256) {
            int q = idx & 63, l = idx >> 6;
            int k0 = 2 * q;
            float2 z0 = tile[k0][l],               z1 = tile[k0 + 1][l];
            float2 m0 = tile[(256 - k0) & 255][l], m1 = tile[255 - k0][l];
            float f0 = (float)k0, f1 = (float)(k0 + 1);
            float4 A = make_float4(0.5f * f0 * (z0.x + m0.x), 0.5f * f0 * (z0.y - m0.y),
                                   0.5f * f1 * (z1.x + m1.x), 0.5f * f1 * (z1.y - m1.y));
            float4 B = make_float4(0.5f * f0 * (z0.y + m0.y), 0.5f * f0 * (m0.x - z0.x),
                                   0.5f * f1 * (z1.y + m1.y), 0.5f * f1 * (m1.x - z1.x));
            *(float4*)&g_S[2 * (size_t)CHS2 + (lineBase + 2 * l) * ZP + k0]     = A;
            *(float4*)&g_S[2 * (size_t)CHS2 + (lineBase + 2 * l + 1) * ZP + k0] = B;
        }
        if (threadIdx.x < 16) {
            int l = threadIdx.x;
            float2 z = tile[128][l];
            g_S[2 * (size_t)CHS2 + (lineBase + 2 * l) * ZP + 128]     = make_float2(z.x * 128.f, 0.f);
            g_S[2 * (size_t)CHS2 + (lineBase + 2 * l + 1) * ZP + 128] = make_float2(z.y * 128.f, 0.f);
        }
    }
}

// Unified forward y-pass:
//   blockIdx.z == 0 : field 0 (X_hat), plain y-FFT in place.
//   blockIdx.z == 1 : fields 1,2 -> fy*FFTy(Y_hat) + FFTy(fz*Z_hat) into g_S[1].
__global__ void __launch_bounds__(256) yfwd_kernel() {
    __shared__ float2 tile[256][17];
    __shared__ float2 stw[256];
    stw[threadIdx.x] = g_tw[threadIdx.x];
    const int line = threadIdx.x & 15;
    const int w    = threadIdx.x >> 4;
    const int zl   = blockIdx.x * 16 + line;
    const bool ok  = zl < RH;
    const size_t rowoff = (size_t)blockIdx.y * XS2 + (size_t)zl;
    const bool merged = blockIdx.z == 1;

    float2 acc[16];
    float2 v[16];
    {
        const float2* row = g_S + (merged ? (size_t)CHS2 : 0) + rowoff;
#pragma unroll
        for (int j = 0; j < 16; j++) v[j] = row[(size_t)(w + 16 * j) * ZP];
    }
    __syncthreads();   // stw ready
    fft16<0>(v);
#pragma unroll
    for (int k = 1; k < 16; k++) v[k] = cmul(v[k], stw[(w * k) & 255]);
#pragma unroll
    for (int k = 0; k < 16; k++) tile[w + 16 * k][line] = v[k];
    __syncthreads();
#pragma unroll
    for (int j = 0; j < 16; j++) v[j] = tile[j + 16 * w][line];
    fft16<0>(v);
    if (!merged) {
        if (ok) {
            float2* dst = g_S + rowoff;
#pragma unroll
            for (int j = 0; j < 16; j++) dst[(size_t)(w + 16 * j) * ZP] = v[j];
        }
        return;
    }
#pragma unroll
    for (int j = 0; j < 16; j++) {
        int e = w + 16 * j;
        float fy = (float)e - (e >= 128 ? 256.f : 0.f);
        acc[j] = make_float2(v[j].x * fy, v[j].y * fy);
    }
    {
        const float2* row = g_S + 2 * (size_t)CHS2 + rowoff;
#pragma unroll
        for (int j = 0; j < 16; j++) v[j] = row[(size_t)(w + 16 * j) * ZP];
    }
    __syncthreads();   // phase-1 tile reads done
    fft16<0>(v);
#pragma unroll
    for (int k = 1; k < 16; k++) v[k] = cmul(v[k], stw[(w * k) & 255]);
#pragma unroll
    for (int k = 0; k < 16; k++) tile[w + 16 * k][line] = v[k];
    __syncthreads();
#pragma unroll
    for (int j = 0; j < 16; j++) v[j] = tile[j + 16 * w][line];
    fft16<0>(v);
    if (ok) {
        float2* dst = g_S + CHS2 + rowoff;
#pragma unroll
        for (int j = 0; j < 16; j++)
            dst[(size_t)(w + 16 * j) * ZP] = make_float2(acc[j].x + v[j].x, acc[j].y + v[j].y);
    }
}

// Inverse y-pass on g_P.
__global__ void __launch_bounds__(256) yinv_kernel() {
    __shared__ float2 tile[256][17];
    __shared__ float2 stw[256];
    stw[threadIdx.x] = g_tw[threadIdx.x];
    const int line = threadIdx.x & 15;
    const int w    = threadIdx.x >> 4;
    const int zl   = blockIdx.x * 16 + line;
    const bool ok  = zl < RH;
    float2* row = g_P + (size_t)blockIdx.y * XS2 + (size_t)zl;
    float2 v[16];
#pragma unroll
    for (int j = 0; j < 16; j++) v[j] = row[(size_t)(w + 16 * j) * ZP];
    __syncthreads();   // stw ready
    fft16<1>(v);
#pragma unroll
    for (int k = 1; k < 16; k++) {
        float2 t = stw[(w * k) & 255];
        t.y = -t.y;
        v[k] = cmul(v[k], t);
    }
#pragma unroll
    for (int k = 0; k < 16; k++) tile[w + 16 * k][line] = v[k];
    __syncthreads();
#pragma unroll
    for (int j = 0; j < 16; j++) v[j] = tile[j + 16 * w][line];
    fft16<1>(v);
    if (ok) {
#pragma unroll
        for (int j = 0; j < 16; j++) row[(size_t)(w + 16 * j) * ZP] = v[j];
    }
}

// Fused forward-x FFT (2 fields) + spectral combine + inverse-x FFT -> g_P.
__global__ void __launch_bounds__(256, 2) xfuse_kernel() {
    __shared__ float2 tile[256][17];
    __shared__ float2 stw[256];
    stw[threadIdx.x] = g_tw[threadIdx.x];
    const int line = threadIdx.x & 15;
    const int w    = threadIdx.x >> 4;
    const int y    = blockIdx.y;
    const int zl   = blockIdx.x * 16 + line;
    const bool ok  = zl < RH;
    const size_t rowbase = (size_t)y * ZP + (size_t)zl;

    const float fy = (float)(y < 128 ? y : y - 256);
    const float fz = (float)zl;
    const float sigf = 20.f / 256.f;
    const float twopi = 6.283185307179586f;
    float aG[16];
#pragma unroll
    for (int j = 0; j < 16; j++) {
        int e = w + 16 * j;
        float fx = (float)e - (e >= 128 ? 256.f : 0.f);
        float d2 = fx * fx + fy * fy + fz * fz;
        aG[j] = twopi * __expf(-0.5f * sigf * sigf * d2);
    }
    float2 acc[16];
#pragma unroll
    for (int j = 0; j < 16; j++) acc[j] = make_float2(0.f, 0.f);

#pragma unroll
    for (int c = 0; c < 2; c++) {
        const float2* src = g_S + (size_t)c * CHS2 + rowbase;
        float2 v[16];
#pragma unroll
        for (int j = 0; j < 16; j++) v[j] = src[(size_t)(w + 16 * j) * XS2];
        __syncthreads();   // prev-iter tile reads done (and stw on iter 0)
        fft16<0>(v);
#pragma unroll
        for (int k = 1; k < 16; k++) v[k] = cmul(v[k], stw[(w * k) & 255]);
#pragma unroll
        for (int k = 0; k < 16; k++) tile[w + 16 * k][line] = v[k];
        __syncthreads();
#pragma unroll
        for (int j = 0; j < 16; j++) v[j] = tile[j + 16 * w][line];
        fft16<0>(v);
#pragma unroll
        for (int j = 0; j < 16; j++) {
            float fc = 1.f;
            if (c == 0) {
                int e = w + 16 * j;
                fc = (float)e - (e >= 128 ? 256.f : 0.f);
            }
            float coef = aG[j] * fc;
            acc[j].x += coef * v[j].y;
            acc[j].y -= coef * v[j].x;
        }
    }
#pragma unroll
    for (int j = 0; j < 16; j++) {
        int e = w + 16 * j;
        float fx = (float)e - (e >= 128 ? 256.f : 0.f);
        float d2 = fx * fx + fy * fy + fz * fz;
        float invL = 1.f / (-(twopi * twopi) * d2 + 1e-6f);
        acc[j].x *= invL;
        acc[j].y *= invL;
    }
    fft16<1>(acc);
#pragma unroll
    for (int k = 1; k < 16; k++) {
        float2 t = stw[(w * k) & 255];
        t.y = -t.y;
        acc[k] = cmul(acc[k], t);
    }
    __syncthreads();   // last fwd-stage tile reads done
#pragma unroll
    for (int k = 0; k < 16; k++) tile[w + 16 * k][line] = acc[k];
    __syncthreads();
#pragma unroll
    for (int j = 0; j < 16; j++) acc[j] = tile[j + 16 * w][line];
    fft16<1>(acc);
    if (ok) {
        float2* dst = g_P + rowbase;
#pragma unroll
        for (int j = 0; j < 16; j++) dst[(size_t)(w + 16 * j) * XS2] = acc[j];
    }
}

// Pack-2 inverse real FFT along z: 32 real output lines/block as 16 complex.
__global__ void __launch_bounds__(256) zinv_kernel(float* __restrict__ out) {
    __shared__ float2 tile[256][17];
    __shared__ float2 stw[256];
    stw[threadIdx.x] = g_tw[threadIdx.x];
    const size_t lineBase = (size_t)blockIdx.x * 32;
    for (int idx = threadIdx.x; idx < 16 * 64; idx += 256) {
        int q = idx & 63, l = idx >> 6;
        int k0 = 2 * q;
        float4 a4 = *(const float4*)&g_P[(lineBase + 2 * l) * ZP + k0];
        float4 b4 = *(const float4*)&g_P[(lineBase + 2 * l + 1) * ZP + k0];
        tile[k0][l]     = make_float2(a4.x - b4.y, a4.y + b4.x);
        tile[k0 + 1][l] = make_float2(a4.z - b4.w, a4.w + b4.z);
        if (k0 > 0) tile[256 - k0][l] = make_float2(a4.x + b4.y, b4.x - a4.y);
        tile[255 - k0][l] = make_float2(a4.z + b4.w, b4.z - a4.w);
    }
    if (threadIdx.x < 16) {
        int l = threadIdx.x;
        float2 A = g_P[(lineBase + 2 * l) * ZP + 128];
        float2 B = g_P[(lineBase + 2 * l + 1) * ZP + 128];
        tile[128][l] = make_float2(A.x - B.y, A.y + B.x);
    }
    __syncthreads();
    const int line = threadIdx.x & 15;
    const int w    = threadIdx.x >> 4;
    float2 v[16];
#pragma unroll
    for (int j = 0; j < 16; j++) v[j] = tile[w + 16 * j][line];
    fft16<1>(v);
#pragma unroll
    for (int k = 1; k < 16; k++) {
        float2 t = stw[(w * k) & 255];
        t.y = -t.y;
        v[k] = cmul(v[k], t);
    }
#pragma unroll
    for (int k = 0; k < 16; k++) tile[w + 16 * k][line] = v[k];
    __syncthreads();
#pragma unroll
    for (int j = 0; j < 16; j++) v[j] = tile[j + 16 * w][line];
    fft16<1>(v);
    __syncthreads();
#pragma unroll
    for (int j = 0; j < 16; j++) tile[w + 16 * j][line] = v[j];
    __syncthreads();
    const float sc = 1.f / 16777216.f;
    for (int idx = threadIdx.x; idx < 16 * 64; idx += 256) {
        int q = idx & 63, l = idx >> 6;
        float2 z0 = tile[4 * q + 0][l], z1 = tile[4 * q + 1][l];
        float2 z2 = tile[4 * q + 2][l], z3 = tile[4 * q + 3][l];
        *(float4*)&out[(lineBase + 2 * l) * 256 + 4 * q] =
            make_float4(z0.x * sc, z1.x * sc, z2.x * sc, z3.x * sc);
        *(float4*)&out[(lineBase + 2 * l + 1) * 256 + 4 * q] =
            make_float4(z0.y * sc, z1.y * sc, z2.y * sc, z3.y * sc);
    }
}

__global__ void interp_kernel(const float* __restrict__ V, const float* __restrict__ phi, int P) {
    int p = blockIdx.x * 256 + threadIdx.x;
    float val = 0.f;
    if (p < P) {
        float px = V[3 * p + 0] * 256.f, py = V[3 * p + 1] * 256.f, pz = V[3 * p + 2] * 256.f;
        float flx = floorf(px), fly = floorf(py), flz = floorf(pz);
        int i0x = (int)flx, i0y = (int)fly, i0z = (int)flz;
        int i1x = ((int)ceilf(px)) & 255, i1y = ((int)ceilf(py)) & 255, i1z = ((int)ceilf(pz)) & 255;
        float f1x = px - flx, f1y = py - fly, f1z = pz - flz;
        float f0x = 1.f - f1x, f0y = 1.f - f1y, f0z = 1.f - f1z;
#pragma unroll
        for (int c = 0; c < 8; c++) {
            const int bx = (c >> 2) & 1, by = (c >> 1) & 1, bz = c & 1;
            float w = (bx ? f1x : f0x) * (by ? f1y : f0y) * (bz ? f1z : f0z);
            int ix = bx ? i1x : i0x, iy = by ? i1y : i0y, iz = bz ? i1z : i0z;
            val += w * phi[((ix << 8) + iy) * 256 + iz];
        }
    }
    __shared__ float red[256];
    red[threadIdx.x] = val;
    __syncthreads();
    for (int s = 128; s > 0; s >>= 1) {
        if (threadIdx.x < s) red[threadIdx.x] += red[threadIdx.x + s];
        __syncthreads();
    }
    if (threadIdx.x == 0) atomicAdd(&g_sum, (double)red[0]);
    if (p == 0) g_phi0 = phi[0];
}

__global__ void finalize_kernel(float* __restrict__ out, int P) {
    float m = (float)(g_sum / (double)P);
    float scale = -0.5f / fabsf(g_phi0 - m);
    size_t i = (size_t)blockIdx.x * 256 + threadIdx.x;
    float4 v = ((float4*)out)[i];
    v.x = (v.x - m) * scale;
    v.y = (v.y - m) * scale;
    v.z = (v.z - m) * scale;
    v.w = (v.w - m) * scale;
    ((float4*)out)[i] = v;
}

// ---------------- launch ----------------
extern "C" void kernel_launch(void* const* d_in, const int* in_sizes, int n_in,
                              void* d_out, int out_size) {
    const float* V = (const float*)d_in[0];
    const float* N = (const float*)d_in[1];
    float* out = (float*)d_out;
    int P = in_sizes[0] / 3;

    init_kernel<<<1, 256>>>();
    zero_kernel<<<49152, 256>>>();                      // Z first, XY last (L2-warm)
    scatter_kernel<<<(P + 127) / 128, 128>>>(V, N, P);

    // forward z: one launch (xy cross-channel pack + z pack-2 with fz folded)
    zfwd_kernel<<<6144, 256>>>();
    // unified forward y (z=0: field 0; z=1: merged fields 1+2)
    yfwd_kernel<<<dim3(9, 256, 2), 256>>>();
    // fused forward x (2 fields) + spectral combine + inverse x -> g_P
    xfuse_kernel<<<dim3(9, 256), 256>>>();
    // inverse y on g_P
    yinv_kernel<<<dim3(9, 256), 256>>>();
    // inverse z (pack-2) -> raw phi in out
    zinv_kernel<<<65536 / 32, 256>>>(out);

    interp_kernel<<<(P + 255) / 256, 256>>>(V, out, P);
    finalize_kernel<<<NVOX / 4 / 256, 256>>>(out, P);
}

// round 16
// speedup vs baseline: 1.4257x; 1.0099x over previous
#include <cuda_runtime.h>
#include <math.h>

#define RR   256
#define RH   129
#define ZP   130                 // padded zh stride (even -> float4-able)
#define NVOX 16777216            // 256^3
#define XS2  33280               // 256*ZP
#define CHS2 8519680             // 256*256*ZP

// ---------------- scratch (device globals: allocation-free) ----------------
__device__ __align__(16) float4 g_g4[NVOX];               // (Nx,Ny,Nz,pad) [x][y][z]
__device__ __align__(16) float2 g_S[3u * CHS2 + 16];      // half-spectra [field][x][y][zh(pad)]
__device__ __align__(16) float2 g_P[CHS2 + 16];           // Phi spectrum [x][y][zh(pad)]
__device__ float2 g_tw[256];                              // W256^m
__device__ double g_sum;
__device__ float  g_phi0;

// ---------------- helpers ----------------
__device__ __forceinline__ float2 cmul(float2 a, float2 b) {
    return make_float2(a.x * b.x - a.y * b.y, a.x * b.y + a.y * b.x);
}

// native 128-bit vector reduction (sm_90+): ONE LSU op per trilinear corner
__device__ __forceinline__ void red_v4(float4* p, float a, float b, float c) {
    float z = 0.f;
    asm volatile("red.global.add.v4.f32 [%0], {%1, %2, %3, %4};"
                 :: "l"(p), "f"(a), "f"(b), "f"(c), "f"(z) : "memory");
}

template<int INV>
__device__ __forceinline__ void fft4(float2& a, float2& b, float2& c, float2& d) {
    float2 t0 = make_float2(a.x + c.x, a.y + c.y);
    float2 t1 = make_float2(a.x - c.x, a.y - c.y);
    float2 t2 = make_float2(b.x + d.x, b.y + d.y);
    float2 t3 = make_float2(b.x - d.x, b.y - d.y);
    float2 t3r = INV ? make_float2(-t3.y, t3.x) : make_float2(t3.y, -t3.x);
    a = make_float2(t0.x + t2.x, t0.y + t2.y);
    c = make_float2(t0.x - t2.x, t0.y - t2.y);
    b = make_float2(t1.x + t3r.x, t1.y + t3r.y);
    d = make_float2(t1.x - t3r.x, t1.y - t3r.y);
}

template<int INV>
__device__ __forceinline__ void fft16(float2 v[16]) {
    const float C1 = 0.9238795325112867f;
    const float S1 = 0.3826834323650898f;
    const float C2 = 0.7071067811865476f;
    const float sg = INV ? 1.f : -1.f;
    const float2 tw1 = make_float2( C1, sg * S1);
    const float2 tw2 = make_float2( C2, sg * C2);
    const float2 tw3 = make_float2( S1, sg * C1);
    const float2 tw4 = make_float2(0.f, sg * 1.f);
    const float2 tw6 = make_float2(-C2, sg * C2);
    const float2 tw9 = make_float2(-C1, -sg * S1);
#pragma unroll
    for (int n1 = 0; n1 < 4; n1++) fft4<INV>(v[n1], v[n1 + 4], v[n1 + 8], v[n1 + 12]);
    v[5]  = cmul(v[5],  tw1);  v[9]  = cmul(v[9],  tw2);  v[13] = cmul(v[13], tw3);
    v[6]  = cmul(v[6],  tw2);  v[10] = cmul(v[10], tw4);  v[14] = cmul(v[14], tw6);
    v[7]  = cmul(v[7],  tw3);  v[11] = cmul(v[11], tw6);  v[15] = cmul(v[15], tw9);
#pragma unroll
    for (int k2 = 0; k2 < 4; k2++) fft4<INV>(v[4 * k2], v[4 * k2 + 1], v[4 * k2 + 2], v[4 * k2 + 3]);
    float2 o[16];
#pragma unroll
    for (int k1 = 0; k1 < 4; k1++)
#pragma unroll
        for (int k2 = 0; k2 < 4; k2++) o[k2 + 4 * k1] = v[k1 + 4 * k2];
#pragma unroll
    for (int i = 0; i < 16; i++) v[i] = o[i];
}

// ---------------- kernels ----------------
__global__ void init_kernel() {
    int i = threadIdx.x;
    double a = -2.0 * 3.14159265358979323846 * (double)i / 256.0;
    double s, c;
    sincos(a, &s, &c);
    g_tw[i] = make_float2((float)c, (float)s);
    if (i == 0) g_sum = 0.0;
}

__global__ void zero_kernel() {
    size_t i = (size_t)blockIdx.x * 256 + threadIdx.x;
    g_g4[i] = make_float4(0.f, 0.f, 0.f, 0.f);
}

__global__ void scatter_kernel(const float* __restrict__ V, const float* __restrict__ N, int P) {
    int p = blockIdx.x * blockDim.x + threadIdx.x;
    if (p >= P) return;
    float px = V[3 * p + 0] * 256.f, py = V[3 * p + 1] * 256.f, pz = V[3 * p + 2] * 256.f;
    float nx = N[3 * p + 0], ny = N[3 * p + 1], nz = N[3 * p + 2];
    float flx = floorf(px), fly = floorf(py), flz = floorf(pz);
    int i0x = (int)flx, i0y = (int)fly, i0z = (int)flz;
    int i1x = ((int)ceilf(px)) & 255, i1y = ((int)ceilf(py)) & 255, i1z = ((int)ceilf(pz)) & 255;
    float f1x = px - flx, f1y = py - fly, f1z = pz - flz;
    float f0x = 1.f - f1x, f0y = 1.f - f1y, f0z = 1.f - f1z;
#pragma unroll
    for (int c = 0; c < 8; c++) {
        const int bx = (c >> 2) & 1, by = (c >> 1) & 1, bz = c & 1;
        float w = (bx ? f1x : f0x) * (by ? f1y : f0y) * (bz ? f1z : f0z);
        int ix = bx ? i1x : i0x, iy = by ? i1y : i0y, iz = bz ? i1z : i0z;
        int vox = ((ix << 8) + iy) * 256 + iz;
        red_v4(&g_g4[vox], nx * w, ny * w, nz * w);   // single RED.128
    }
}

// Unified forward z-FFT over 32 spatial lines per block, 3 FFT phases:
//   Phase A (x2): xy channels via cross-channel complex packing
//     ((Nx,Ny) IS Nx + i*Ny; FFT + Hermitian unpack -> g_S[0], g_S[1]), 16 lines each.
//   Phase B: z channel via pack-2 real FFT (fz folded) -> g_S[2], 32 lines.
//   Phase B's .z re-reads hit L2 (block footprint just loaded in phase A).
__global__ void __launch_bounds__(256) zfwd_kernel() {
    __shared__ float2 tile[256][17];
    __shared__ float2 stw[256];
    stw[threadIdx.x] = g_tw[threadIdx.x];
    const int line = threadIdx.x & 15;
    const int w    = threadIdx.x >> 4;
    const size_t lineBase = (size_t)blockIdx.x * 32;
    float2 v[16];

#pragma unroll
    for (int sub = 0; sub < 2; sub++) {
        const size_t lb = lineBase + sub * 16;
        __syncthreads();   // stw ready / prev unpack reads done
        for (int idx = threadIdx.x; idx < 16 * 256; idx += 256) {
            int z = idx & 255, l = idx >> 8;
            float4 d = g_g4[(lb + l) * 256 + z];
            tile[z][l] = make_float2(d.x, d.y);
        }
        __syncthreads();
#pragma unroll
        for (int j = 0; j < 16; j++) v[j] = tile[w + 16 * j][line];
        fft16<0>(v);
#pragma unroll
        for (int k = 1; k < 16; k++) v[k] = cmul(v[k], stw[(w * k) & 255]);
#pragma unroll
        for (int k = 0; k < 16; k++) tile[w + 16 * k][line] = v[k];
        __syncthreads();
#pragma unroll
        for (int j = 0; j < 16; j++) v[j] = tile[j + 16 * w][line];
        fft16<0>(v);
        __syncthreads();
#pragma unroll
        for (int j = 0; j < 16; j++) tile[w + 16 * j][line] = v[j];   // Z[e=w+16j]
        __syncthreads();
        // X_hat[k]=(Z[k]+conj(Z[m]))/2, Y_hat[k]=(Z[k]-conj(Z[m]))/2i, m=(256-k)&255
        for (int idx = threadIdx.x; idx < 16 * 64; idx += 256) {
            int q = idx & 63, l = idx >> 6;
            int k0 = 2 * q;
            float2 z0 = tile[k0][l],               z1 = tile[k0 + 1][l];
            float2 m0 = tile[(256 - k0) & 255][l], m1 = tile[255 - k0][l];
            float4 A = make_float4(0.5f * (z0.x + m0.x), 0.5f * (z0.y - m0.y),
                                   0.5f * (z1.x + m1.x), 0.5f * (z1.y - m1.y));
            float4 B = make_float4(0.5f * (z0.y + m0.y), 0.5f * (m0.x - z0.x),
                                   0.5f * (z1.y + m1.y), 0.5f * (m1.x - z1.x));
            *(float4*)&g_S[(lb + l) * ZP + k0]        = A;
            *(float4*)&g_S[CHS2 + (lb + l) * ZP + k0] = B;
        }
        if (threadIdx.x < 16) {
            int l = threadIdx.x;
            float2 z = tile[128][l];
            g_S[(lb + l) * ZP + 128]        = make_float2(z.x, 0.f);
            g_S[CHS2 + (lb + l) * ZP + 128] = make_float2(z.y, 0.f);
        }
    }

    // Phase B: z channel, pack-2 over the same 32 lines
    __syncthreads();
    for (int idx = threadIdx.x; idx < 16 * 256; idx += 256) {
        int z = idx & 255, l = idx >> 8;
        float a = g_g4[(lineBase + 2 * l) * 256 + z].z;      // L2-hot
        float b = g_g4[(lineBase + 2 * l + 1) * 256 + z].z;
        tile[z][l] = make_float2(a, b);
    }
    __syncthreads();
#pragma unroll
    for (int j = 0; j < 16; j++) v[j] = tile[w + 16 * j][line];
    fft16<0>(v);
#pragma unroll
    for (int k = 1; k < 16; k++) v[k] = cmul(v[k], stw[(w * k) & 255]);
#pragma unroll
    for (int k = 0; k < 16; k++) tile[w + 16 * k][line] = v[k];
    __syncthreads();
#pragma unroll
    for (int j = 0; j < 16; j++) v[j] = tile[j + 16 * w][line];
    fft16<0>(v);
    __syncthreads();
#pragma unroll
    for (int j = 0; j < 16; j++) tile[w + 16 * j][line] = v[j];
    __syncthreads();
    for (int idx = threadIdx.x; idx < 16 * 64; idx += 256) {
        int q = idx & 63, l = idx >> 6;
        int k0 = 2 * q;
        float2 z0 = tile[k0][l],               z1 = tile[k0 + 1][l];
        float2 m0 = tile[(256 - k0) & 255][l], m1 = tile[255 - k0][l];
        float f0 = (float)k0, f1 = (float)(k0 + 1);
        float4 A = make_float4(0.5f * f0 * (z0.x + m0.x), 0.5f * f0 * (z0.y - m0.y),
                               0.5f * f1 * (z1.x + m1.x), 0.5f * f1 * (z1.y - m1.y));
        float4 B = make_float4(0.5f * f0 * (z0.y + m0.y), 0.5f * f0 * (m0.x - z0.x),
                               0.5f * f1 * (z1.y + m1.y), 0.5f * f1 * (m1.x - z1.x));
        *(float4*)&g_S[2 * (size_t)CHS2 + (lineBase + 2 * l) * ZP + k0]     = A;
        *(float4*)&g_S[2 * (size_t)CHS2 + (lineBase + 2 * l + 1) * ZP + k0] = B;
    }
    if (threadIdx.x < 16) {
        int l = threadIdx.x;
        float2 z = tile[128][l];
        g_S[2 * (size_t)CHS2 + (lineBase + 2 * l) * ZP + 128]     = make_float2(z.x * 128.f, 0.f);
        g_S[2 * (size_t)CHS2 + (lineBase + 2 * l + 1) * ZP + 128] = make_float2(z.y * 128.f, 0.f);
    }
}

// Unified forward y-pass:
//   blockIdx.z == 0 : field 0 (X_hat), plain y-FFT in place.
//   blockIdx.z == 1 : fields 1,2 -> fy*FFTy(Y_hat) + FFTy(fz*Z_hat) into g_S[1].
__global__ void __launch_bounds__(256) yfwd_kernel() {
    __shared__ float2 tile[256][17];
    __shared__ float2 stw[256];
    stw[threadIdx.x] = g_tw[threadIdx.x];
    const int line = threadIdx.x & 15;
    const int w    = threadIdx.x >> 4;
    const int zl   = blockIdx.x * 16 + line;
    const bool ok  = zl < RH;
    const size_t rowoff = (size_t)blockIdx.y * XS2 + (size_t)zl;
    const bool merged = blockIdx.z == 1;

    float2 acc[16];
    float2 v[16];
    {
        const float2* row = g_S + (merged ? (size_t)CHS2 : 0) + rowoff;
#pragma unroll
        for (int j = 0; j < 16; j++) v[j] = row[(size_t)(w + 16 * j) * ZP];
    }
    __syncthreads();   // stw ready
    fft16<0>(v);
#pragma unroll
    for (int k = 1; k < 16; k++) v[k] = cmul(v[k], stw[(w * k) & 255]);
#pragma unroll
    for (int k = 0; k < 16; k++) tile[w + 16 * k][line] = v[k];
    __syncthreads();
#pragma unroll
    for (int j = 0; j < 16; j++) v[j] = tile[j + 16 * w][line];
    fft16<0>(v);
    if (!merged) {
        if (ok) {
            float2* dst = g_S + rowoff;
#pragma unroll
            for (int j = 0; j < 16; j++) dst[(size_t)(w + 16 * j) * ZP] = v[j];
        }
        return;
    }
#pragma unroll
    for (int j = 0; j < 16; j++) {
        int e = w + 16 * j;
        float fy = (float)e - (e >= 128 ? 256.f : 0.f);
        acc[j] = make_float2(v[j].x * fy, v[j].y * fy);
    }
    {
        const float2* row = g_S + 2 * (size_t)CHS2 + rowoff;
#pragma unroll
        for (int j = 0; j < 16; j++) v[j] = row[(size_t)(w + 16 * j) * ZP];
    }
    __syncthreads();   // phase-1 tile reads done
    fft16<0>(v);
#pragma unroll
    for (int k = 1; k < 16; k++) v[k] = cmul(v[k], stw[(w * k) & 255]);
#pragma unroll
    for (int k = 0; k < 16; k++) tile[w + 16 * k][line] = v[k];
    __syncthreads();
#pragma unroll
    for (int j = 0; j < 16; j++) v[j] = tile[j + 16 * w][line];
    fft16<0>(v);
    if (ok) {
        float2* dst = g_S + CHS2 + rowoff;
#pragma unroll
        for (int j = 0; j < 16; j++)
            dst[(size_t)(w + 16 * j) * ZP] = make_float2(acc[j].x + v[j].x, acc[j].y + v[j].y);
    }
}

// Inverse y-pass on g_P.
__global__ void __launch_bounds__(256) yinv_kernel() {
    __shared__ float2 tile[256][17];
    __shared__ float2 stw[256];
    stw[threadIdx.x] = g_tw[threadIdx.x];
    const int line = threadIdx.x & 15;
    const int w    = threadIdx.x >> 4;
    const int zl   = blockIdx.x * 16 + line;
    const bool ok  = zl < RH;
    float2* row = g_P + (size_t)blockIdx.y * XS2 + (size_t)zl;
    float2 v[16];
#pragma unroll
    for (int j = 0; j < 16; j++) v[j] = row[(size_t)(w + 16 * j) * ZP];
    __syncthreads();   // stw ready
    fft16<1>(v);
#pragma unroll
    for (int k = 1; k < 16; k++) {
        float2 t = stw[(w * k) & 255];
        t.y = -t.y;
        v[k] = cmul(v[k], t);
    }
#pragma unroll
    for (int k = 0; k < 16; k++) tile[w + 16 * k][line] = v[k];
    __syncthreads();
#pragma unroll
    for (int j = 0; j < 16; j++) v[j] = tile[j + 16 * w][line];
    fft16<1>(v);
    if (ok) {
#pragma unroll
        for (int j = 0; j < 16; j++) row[(size_t)(w + 16 * j) * ZP] = v[j];
    }
}

// Fused forward-x FFT (2 fields) + spectral combine + inverse-x FFT -> g_P.
__global__ void __launch_bounds__(256, 2) xfuse_kernel() {
    __shared__ float2 tile[256][17];
    __shared__ float2 stw[256];
    stw[threadIdx.x] = g_tw[threadIdx.x];
    const int line = threadIdx.x & 15;
    const int w    = threadIdx.x >> 4;
    const int y    = blockIdx.y;
    const int zl   = blockIdx.x * 16 + line;
    const bool ok  = zl < RH;
    const size_t rowbase = (size_t)y * ZP + (size_t)zl;

    const float fy = (float)(y < 128 ? y : y - 256);
    const float fz = (float)zl;
    const float sigf = 20.f / 256.f;
    const float twopi = 6.283185307179586f;
    float aG[16];
#pragma unroll
    for (int j = 0; j < 16; j++) {
        int e = w + 16 * j;
        float fx = (float)e - (e >= 128 ? 256.f : 0.f);
        float d2 = fx * fx + fy * fy + fz * fz;
        aG[j] = twopi * __expf(-0.5f * sigf * sigf * d2);
    }
    float2 acc[16];
#pragma unroll
    for (int j = 0; j < 16; j++) acc[j] = make_float2(0.f, 0.f);

#pragma unroll
    for (int c = 0; c < 2; c++) {
        const float2* src = g_S + (size_t)c * CHS2 + rowbase;
        float2 v[16];
#pragma unroll
        for (int j = 0; j < 16; j++) v[j] = src[(size_t)(w + 16 * j) * XS2];
        __syncthreads();   // prev-iter tile reads done (and stw on iter 0)
        fft16<0>(v);
#pragma unroll
        for (int k = 1; k < 16; k++) v[k] = cmul(v[k], stw[(w * k) & 255]);
#pragma unroll
        for (int k = 0; k < 16; k++) tile[w + 16 * k][line] = v[k];
        __syncthreads();
#pragma unroll
        for (int j = 0; j < 16; j++) v[j] = tile[j + 16 * w][line];
        fft16<0>(v);
#pragma unroll
        for (int j = 0; j < 16; j++) {
            float fc = 1.f;
            if (c == 0) {
                int e = w + 16 * j;
                fc = (float)e - (e >= 128 ? 256.f : 0.f);
            }
            float coef = aG[j] * fc;
            acc[j].x += coef * v[j].y;
            acc[j].y -= coef * v[j].x;
        }
    }
#pragma unroll
    for (int j = 0; j < 16; j++) {
        int e = w + 16 * j;
        float fx = (float)e - (e >= 128 ? 256.f : 0.f);
        float d2 = fx * fx + fy * fy + fz * fz;
        float invL = 1.f / (-(twopi * twopi) * d2 + 1e-6f);
        acc[j].x *= invL;
        acc[j].y *= invL;
    }
    fft16<1>(acc);
#pragma unroll
    for (int k = 1; k < 16; k++) {
        float2 t = stw[(w * k) & 255];
        t.y = -t.y;
        acc[k] = cmul(acc[k], t);
    }
    __syncthreads();   // last fwd-stage tile reads done
#pragma unroll
    for (int k = 0; k < 16; k++) tile[w + 16 * k][line] = acc[k];
    __syncthreads();
#pragma unroll
    for (int j = 0; j < 16; j++) acc[j] = tile[j + 16 * w][line];
    fft16<1>(acc);
    if (ok) {
        float2* dst = g_P + rowbase;
#pragma unroll
        for (int j = 0; j < 16; j++) dst[(size_t)(w + 16 * j) * XS2] = acc[j];
    }
}

// Pack-2 inverse real FFT along z: 32 real output lines/block as 16 complex.
__global__ void __launch_bounds__(256) zinv_kernel(float* __restrict__ out) {
    __shared__ float2 tile[256][17];
    __shared__ float2 stw[256];
    stw[threadIdx.x] = g_tw[threadIdx.x];
    const size_t lineBase = (size_t)blockIdx.x * 32;
    for (int idx = threadIdx.x; idx < 16 * 64; idx += 256) {
        int q = idx & 63, l = idx >> 6;
        int k0 = 2 * q;
        float4 a4 = *(const float4*)&g_P[(lineBase + 2 * l) * ZP + k0];
        float4 b4 = *(const float4*)&g_P[(lineBase + 2 * l + 1) * ZP + k0];
        tile[k0][l]     = make_float2(a4.x - b4.y, a4.y + b4.x);
        tile[k0 + 1][l] = make_float2(a4.z - b4.w, a4.w + b4.z);
        if (k0 > 0) tile[256 - k0][l] = make_float2(a4.x + b4.y, b4.x - a4.y);
        tile[255 - k0][l] = make_float2(a4.z + b4.w, b4.z - a4.w);
    }
    if (threadIdx.x < 16) {
        int l = threadIdx.x;
        float2 A = g_P[(lineBase + 2 * l) * ZP + 128];
        float2 B = g_P[(lineBase + 2 * l + 1) * ZP + 128];
        tile[128][l] = make_float2(A.x - B.y, A.y + B.x);
    }
    __syncthreads();
    const int line = threadIdx.x & 15;
    const int w    = threadIdx.x >> 4;
    float2 v[16];
#pragma unroll
    for (int j = 0; j < 16; j++) v[j] = tile[w + 16 * j][line];
    fft16<1>(v);
#pragma unroll
    for (int k = 1; k < 16; k++) {
        float2 t = stw[(w * k) & 255];
        t.y = -t.y;
        v[k] = cmul(v[k], t);
    }
#pragma unroll
    for (int k = 0; k < 16; k++) tile[w + 16 * k][line] = v[k];
    __syncthreads();
#pragma unroll
    for (int j = 0; j < 16; j++) v[j] = tile[j + 16 * w][line];
    fft16<1>(v);
    __syncthreads();
#pragma unroll
    for (int j = 0; j < 16; j++) tile[w + 16 * j][line] = v[j];
    __syncthreads();
    const float sc = 1.f / 16777216.f;
    for (int idx = threadIdx.x; idx < 16 * 64; idx += 256) {
        int q = idx & 63, l = idx >> 6;
        float2 z0 = tile[4 * q + 0][l], z1 = tile[4 * q + 1][l];
        float2 z2 = tile[4 * q + 2][l], z3 = tile[4 * q + 3][l];
        *(float4*)&out[(lineBase + 2 * l) * 256 + 4 * q] =
            make_float4(z0.x * sc, z1.x * sc, z2.x * sc, z3.x * sc);
        *(float4*)&out[(lineBase + 2 * l + 1) * 256 + 4 * q] =
            make_float4(z0.y * sc, z1.y * sc, z2.y * sc, z3.y * sc);
    }
}

__global__ void interp_kernel(const float* __restrict__ V, const float* __restrict__ phi, int P) {
    int p = blockIdx.x * 256 + threadIdx.x;
    float val = 0.f;
    if (p < P) {
        float px = V[3 * p + 0] * 256.f, py = V[3 * p + 1] * 256.f, pz = V[3 * p + 2] * 256.f;
        float flx = floorf(px), fly = floorf(py), flz = floorf(pz);
        int i0x = (int)flx, i0y = (int)fly, i0z = (int)flz;
        int i1x = ((int)ceilf(px)) & 255, i1y = ((int)ceilf(py)) & 255, i1z = ((int)ceilf(pz)) & 255;
        float f1x = px - flx, f1y = py - fly, f1z = pz - flz;
        float f0x = 1.f - f1x, f0y = 1.f - f1y, f0z = 1.f - f1z;
#pragma unroll
        for (int c = 0; c < 8; c++) {
            const int bx = (c >> 2) & 1, by = (c >> 1) & 1, bz = c & 1;
            float w = (bx ? f1x : f0x) * (by ? f1y : f0y) * (bz ? f1z : f0z);
            int ix = bx ? i1x : i0x, iy = by ? i1y : i0y, iz = bz ? i1z : i0z;
            val += w * phi[((ix << 8) + iy) * 256 + iz];
        }
    }
    __shared__ float red[256];
    red[threadIdx.x] = val;
    __syncthreads();
    for (int s = 128; s > 0; s >>= 1) {
        if (threadIdx.x < s) red[threadIdx.x] += red[threadIdx.x + s];
        __syncthreads();
    }
    if (threadIdx.x == 0) atomicAdd(&g_sum, (double)red[0]);
    if (p == 0) g_phi0 = phi[0];
}

__global__ void finalize_kernel(float* __restrict__ out, int P) {
    float m = (float)(g_sum / (double)P);
    float scale = -0.5f / fabsf(g_phi0 - m);
    size_t i = (size_t)blockIdx.x * 256 + threadIdx.x;
    float4 v = ((float4*)out)[i];
    v.x = (v.x - m) * scale;
    v.y = (v.y - m) * scale;
    v.z = (v.z - m) * scale;
    v.w = (v.w - m) * scale;
    ((float4*)out)[i] = v;
}

// ---------------- launch ----------------
extern "C" void kernel_launch(void* const* d_in, const int* in_sizes, int n_in,
                              void* d_out, int out_size) {
    const float* V = (const float*)d_in[0];
    const float* N = (const float*)d_in[1];
    float* out = (float*)d_out;
    int P = in_sizes[0] / 3;

    init_kernel<<<1, 256>>>();
    zero_kernel<<<NVOX / 256, 256>>>();                 // last-zeroed half stays L2-warm
    scatter_kernel<<<(P + 127) / 128, 128>>>(V, N, P);

    // forward z: one launch, 32 lines/block, 3 FFT phases (xy pack x2 + z pack-2)
    zfwd_kernel<<<2048, 256>>>();
    // unified forward y (z=0: field 0; z=1: merged fields 1+2)
    yfwd_kernel<<<dim3(9, 256, 2), 256>>>();
    // fused forward x (2 fields) + spectral combine + inverse x -> g_P
    xfuse_kernel<<<dim3(9, 256), 256>>>();
    // inverse y on g_P
    yinv_kernel<<<dim3(9, 256), 256>>>();
    // inverse z (pack-2) -> raw phi in out
    zinv_kernel<<<65536 / 32, 256>>>(out);

    interp_kernel<<<(P + 255) / 256, 256>>>(V, out, P);
    finalize_kernel<<<NVOX / 4 / 256, 256>>>(out, P);
}